// round 13
// baseline (speedup 1.0000x reference)
#include <cuda_runtime.h>
#include <cuda_bf16.h>

// Problem constants (BS=16, Q=1024, K=256, T=128)
#define NROWS 16384     // BS*Q rows of the cost matrix
#define KCLS  256       // classes
#define MCOLS 2048      // BS*T columns
#define W     8         // warps per block
#define R     2         // rows per warp
#define ROWS_PB (W*R)   // 16 rows per block

// cost = 5*L1 - prob[id] - 2*giou
//
// 1-D GIoU with two identities:
//   hull - inter_raw == |x0-t0| + |x1-t1| == d   (per-coordinate max-min = abs)
//   giou = inter/uni - (hull-uni)/hull
//        = (inter*hull - (hull-uni)*uni) / (uni*hull)   -> single RCP
__device__ __forceinline__ float costf(float x0, float x1, float a1,
                                       float t0, float t1, float a2, float p)
{
    float s0    = x0 - t0;
    float s1    = x1 - t1;
    float d     = fabsf(s0) + fabsf(s1);      // FADD with |.| source modifiers
    float lt    = fmaxf(x0, t0);
    float rb    = fminf(x1, t1);
    float ir    = rb - lt;                    // inter (unclamped)
    float hull  = d + ir;                     // identity: hull = d + inter_raw
    float inter = fmaxf(ir, 0.0f);
    float uni   = (a1 + a2) - inter;
    float hu    = hull - uni;
    float num   = inter * hull - hu * uni;    // FMUL + FFMA
    float g     = __fdividef(num, uni * hull);// FMUL + MUFU.RCP + FMUL
    return fmaf(-2.0f, g, fmaf(5.0f, d, -p));
}

__global__ __launch_bounds__(256, 4)
void matcher_cost_kernel(const float* __restrict__ logits,      // [16384,256]
                         const float* __restrict__ pred_boxes,  // [16384,2] (mid,w)
                         const float* __restrict__ tgt_boxes,   // [2048,2]  (x0,x1)
                         const int*   __restrict__ tgt_labels,  // [2048]
                         float*       __restrict__ out)         // [16384,2048]
{
    // Dynamic shared, 48 KiB:
    //   t0v/t1v/a2v : SoA target coords + area  (3 * 8 KiB)
    //   idv         : target class ids          (8 KiB)
    //   probT       : [W][KCLS][R] softmax, transposed so one LDS.64
    //                 gathers a class's prob for both rows (16 KiB)
    extern __shared__ float sm[];
    float* t0v   = sm;
    float* t1v   = sm + MCOLS;
    float* a2v   = sm + 2 * MCOLS;
    int*   idv   = (int*)(sm + 3 * MCOLS);
    float* probT = sm + 4 * MCOLS;

    const int tid  = threadIdx.x;
    const int lane = tid & 31;
    const int w    = tid >> 5;

    // ---- stage targets as SoA (conflict-free vector reads later) ----
    #pragma unroll
    for (int m = tid; m < MCOLS; m += 256) {
        float2 tb = reinterpret_cast<const float2*>(tgt_boxes)[m];
        t0v[m] = tb.x;
        t1v[m] = tb.y;
        a2v[m] = tb.y - tb.x;
        idv[m] = tgt_labels[m];
    }

    // ---- softmax for R=2 rows per warp; lane owns classes c = lane + 32j ----
    const int row0 = blockIdx.x * ROWS_PB + w * R;
    float* myprob = probT + w * (KCLS * R);

    float  x0v[R], x1v[R], a1v[R];
    float2 e2[8];                        // per class-slot j: prob for rows 0,1

    #pragma unroll
    for (int r = 0; r < R; r++) {
        const int n = row0 + r;
        const float* lrow = logits + (size_t)n * KCLS;

        float v[8];
        #pragma unroll
        for (int j = 0; j < 8; j++)
            v[j] = lrow[lane + 32 * j];          // fully coalesced LDG.32

        float mx = v[0];
        #pragma unroll
        for (int j = 1; j < 8; j++) mx = fmaxf(mx, v[j]);
        #pragma unroll
        for (int off = 16; off; off >>= 1)
            mx = fmaxf(mx, __shfl_xor_sync(0xffffffffu, mx, off));

        float e[8], s = 0.0f;
        #pragma unroll
        for (int j = 0; j < 8; j++) { e[j] = __expf(v[j] - mx); s += e[j]; }
        #pragma unroll
        for (int off = 16; off; off >>= 1)
            s += __shfl_xor_sync(0xffffffffu, s, off);

        float inv = __fdividef(1.0f, s);
        #pragma unroll
        for (int j = 0; j < 8; j++) {
            float p = e[j] * inv;
            if (r == 0) e2[j].x = p; else e2[j].y = p;
        }

        float2 pb = reinterpret_cast<const float2*>(pred_boxes)[n];
        x0v[r] = pb.x - 0.5f * pb.y;
        x1v[r] = pb.x + 0.5f * pb.y;
        a1v[r] = x1v[r] - x0v[r];
    }

    // probT[class][row0,row1] as one STS.64 per class slot (2-way max conflict)
    #pragma unroll
    for (int j = 0; j < 8; j++)
        *reinterpret_cast<float2*>(myprob + (lane + 32 * j) * R) = e2[j];

    __syncthreads();

    // ---- main loop: lane emits 4 consecutive cols x 2 rows per tile ----
    const size_t obase = (size_t)row0 * MCOLS;

    #pragma unroll 2
    for (int kk = 0; kk < MCOLS / 128; kk++) {
        const int m = kk * 128 + lane * 4;

        // conflict-free SoA vector loads of 4 consecutive targets
        float4 ta = *reinterpret_cast<const float4*>(t0v + m);
        float4 tb = *reinterpret_cast<const float4*>(t1v + m);
        float4 tz = *reinterpret_cast<const float4*>(a2v + m);
        int4   ti = *reinterpret_cast<const int4*>(idv + m);

        // one LDS.64 per class: prob for both rows at once
        float2 p0 = *reinterpret_cast<const float2*>(myprob + ti.x * R);
        float2 p1 = *reinterpret_cast<const float2*>(myprob + ti.y * R);
        float2 p2 = *reinterpret_cast<const float2*>(myprob + ti.z * R);
        float2 p3 = *reinterpret_cast<const float2*>(myprob + ti.w * R);

        #pragma unroll
        for (int r = 0; r < R; r++) {
            const float x0 = x0v[r], x1 = x1v[r], a1 = a1v[r];
            float4 res;
            res.x = costf(x0, x1, a1, ta.x, tb.x, tz.x, r == 0 ? p0.x : p0.y);
            res.y = costf(x0, x1, a1, ta.y, tb.y, tz.y, r == 0 ? p1.x : p1.y);
            res.z = costf(x0, x1, a1, ta.z, tb.z, tz.z, r == 0 ? p2.x : p2.y);
            res.w = costf(x0, x1, a1, ta.w, tb.w, tz.w, r == 0 ? p3.x : p3.y);
            *reinterpret_cast<float4*>(out + obase + (size_t)r * MCOLS + m) = res;
        }
    }
}

extern "C" void kernel_launch(void* const* d_in, const int* in_sizes, int n_in,
                              void* d_out, int out_size)
{
    // Identify inputs by element count (all distinct):
    //   pred_logits 4194304 f32, pred_boxes 32768 f32,
    //   tgt_boxes 4096 f32, tgt_labels 2048 i32
    const float* logits = nullptr;
    const float* pboxes = nullptr;
    const float* tboxes = nullptr;
    const int*   tlabel = nullptr;
    for (int i = 0; i < n_in; i++) {
        switch (in_sizes[i]) {
            case 4194304: logits = (const float*)d_in[i]; break;
            case 32768:   pboxes = (const float*)d_in[i]; break;
            case 4096:    tboxes = (const float*)d_in[i]; break;
            case 2048:    tlabel = (const int*)  d_in[i]; break;
            default: break;
        }
    }

    const int smem = 48 * 1024;  // 32 KiB targets SoA+ids + 16 KiB probT
    cudaFuncSetAttribute(matcher_cost_kernel,
                         cudaFuncAttributeMaxDynamicSharedMemorySize, smem);

    dim3 grid(NROWS / ROWS_PB);  // 1024 blocks
    dim3 block(256);
    matcher_cost_kernel<<<grid, block, smem>>>(logits, pboxes, tboxes, tlabel,
                                               (float*)d_out);
}

// round 17
// speedup vs baseline: 1.3997x; 1.3997x over previous
#include <cuda_runtime.h>
#include <cuda_bf16.h>

// Problem constants (BS=16, Q=1024, K=256, T=128)
#define NROWS 16384     // BS*Q rows of the cost matrix
#define KCLS  256       // classes
#define MCOLS 2048      // BS*T columns
#define W     8         // warps per block
#define R     4         // rows per warp
#define ROWS_PB (W*R)   // 32 rows per block

// cost = 5*L1 - prob[id] - 2*giou
//
// 1-D GIoU with two identities:
//   hull - inter_raw == |x0-t0| + |x1-t1| == d   (per-coordinate max-min = abs)
//   giou = inter/uni - (hull-uni)/hull
//        = (inter*hull - (hull-uni)*uni) / (uni*hull)   -> single RCP
__device__ __forceinline__ float costf(float x0, float x1, float a1,
                                       float t0, float t1, float a2, float p)
{
    float s0    = x0 - t0;
    float s1    = x1 - t1;
    float d     = fabsf(s0) + fabsf(s1);       // FADD with |.| source modifiers
    float lt    = fmaxf(x0, t0);
    float rb    = fminf(x1, t1);
    float ir    = rb - lt;                     // inter (unclamped)
    float hull  = d + ir;                      // identity: hull = d + inter_raw
    float inter = fmaxf(ir, 0.0f);
    float uni   = (a1 + a2) - inter;
    float hu    = hull - uni;
    float num   = inter * hull - hu * uni;     // FMUL + FFMA
    float g     = __fdividef(num, uni * hull); // FMUL + MUFU.RCP + FMUL
    return fmaf(-2.0f, g, fmaf(5.0f, d, -p)); // 2x FFMA
}

__global__ __launch_bounds__(256, 3)
void matcher_cost_kernel(const float* __restrict__ logits,      // [16384,256]
                         const float* __restrict__ pred_boxes,  // [16384,2] (mid,w)
                         const float* __restrict__ tgt_boxes,   // [2048,2]  (x0,x1)
                         const int*   __restrict__ tgt_labels,  // [2048]
                         float*       __restrict__ out)         // [16384,2048]
{
    // Dynamic shared, 64 KiB total:
    //   t0v/t1v/a2v : SoA target coords + area  (3 * 8 KiB)
    //   idv         : target class ids          (8 KiB)
    //   probT       : [W][KCLS][R] softmax, transposed so one LDS.128
    //                 gathers a class's prob for all 4 rows (32 KiB)
    extern __shared__ float sm[];
    float* t0v   = sm;
    float* t1v   = sm + MCOLS;
    float* a2v   = sm + 2 * MCOLS;
    int*   idv   = (int*)(sm + 3 * MCOLS);
    float* probT = sm + 4 * MCOLS;

    const int tid  = threadIdx.x;
    const int lane = tid & 31;
    const int w    = tid >> 5;

    // ---- stage targets as SoA (conflict-free vector reads later) ----
    #pragma unroll
    for (int m = tid; m < MCOLS; m += 256) {
        float2 tb = reinterpret_cast<const float2*>(tgt_boxes)[m];
        t0v[m] = tb.x;
        t1v[m] = tb.y;
        a2v[m] = tb.y - tb.x;
        idv[m] = tgt_labels[m];
    }

    // ---- softmax for R=4 rows per warp; lane owns classes c = lane + 32j ----
    const int row0 = blockIdx.x * ROWS_PB + w * R;
    float* myprob = probT + w * (KCLS * R);

    float  x0v[R], x1v[R], a1v[R];
    float4 e4[8];                       // per class-slot j: prob for rows 0..3

    #pragma unroll
    for (int r = 0; r < R; r++) {
        const int n = row0 + r;
        const float* lrow = logits + (size_t)n * KCLS;

        float v[8];
        #pragma unroll
        for (int j = 0; j < 8; j++)
            v[j] = lrow[lane + 32 * j];          // fully coalesced LDG.32

        float mx = v[0];
        #pragma unroll
        for (int j = 1; j < 8; j++) mx = fmaxf(mx, v[j]);
        #pragma unroll
        for (int off = 16; off; off >>= 1)
            mx = fmaxf(mx, __shfl_xor_sync(0xffffffffu, mx, off));

        float e[8], s = 0.0f;
        #pragma unroll
        for (int j = 0; j < 8; j++) { e[j] = __expf(v[j] - mx); s += e[j]; }
        #pragma unroll
        for (int off = 16; off; off >>= 1)
            s += __shfl_xor_sync(0xffffffffu, s, off);

        float inv = __fdividef(1.0f, s);
        #pragma unroll
        for (int j = 0; j < 8; j++) {
            float p = e[j] * inv;
            if      (r == 0) e4[j].x = p;
            else if (r == 1) e4[j].y = p;
            else if (r == 2) e4[j].z = p;
            else             e4[j].w = p;
        }

        float2 pb = reinterpret_cast<const float2*>(pred_boxes)[n];
        x0v[r] = pb.x - 0.5f * pb.y;
        x1v[r] = pb.x + 0.5f * pb.y;
        a1v[r] = x1v[r] - x0v[r];
    }

    // probT[class][row0..3] as one STS.128 per class slot.
    // class c = lane + 32j -> word base c*4 -> bank group = lane&7 (4-way max).
    #pragma unroll
    for (int j = 0; j < 8; j++)
        *reinterpret_cast<float4*>(myprob + (lane + 32 * j) * R) = e4[j];

    __syncthreads();

    // ---- main loop: each lane emits 4 consecutive cols x 4 rows per tile ----
    const size_t obase = (size_t)row0 * MCOLS;

    for (int kk = 0; kk < MCOLS / 128; kk++) {
        const int m = kk * 128 + lane * 4;

        // conflict-free SoA vector loads of 4 consecutive targets
        float4 ta = *reinterpret_cast<const float4*>(t0v + m);
        float4 tb = *reinterpret_cast<const float4*>(t1v + m);
        float4 tz = *reinterpret_cast<const float4*>(a2v + m);
        int4   ti = *reinterpret_cast<const int4*>(idv + m);

        // one vector gather per class: prob for all 4 rows at once
        float4 p0 = *reinterpret_cast<const float4*>(myprob + ti.x * R);
        float4 p1 = *reinterpret_cast<const float4*>(myprob + ti.y * R);
        float4 p2 = *reinterpret_cast<const float4*>(myprob + ti.z * R);
        float4 p3 = *reinterpret_cast<const float4*>(myprob + ti.w * R);

        const float pa0[4] = {p0.x, p0.y, p0.z, p0.w};
        const float pa1[4] = {p1.x, p1.y, p1.z, p1.w};
        const float pa2[4] = {p2.x, p2.y, p2.z, p2.w};
        const float pa3[4] = {p3.x, p3.y, p3.z, p3.w};

        #pragma unroll
        for (int r = 0; r < R; r++) {
            const float x0 = x0v[r], x1 = x1v[r], a1 = a1v[r];
            float4 res;
            res.x = costf(x0, x1, a1, ta.x, tb.x, tz.x, pa0[r]);
            res.y = costf(x0, x1, a1, ta.y, tb.y, tz.y, pa1[r]);
            res.z = costf(x0, x1, a1, ta.z, tb.z, tz.z, pa2[r]);
            res.w = costf(x0, x1, a1, ta.w, tb.w, tz.w, pa3[r]);
            *reinterpret_cast<float4*>(out + obase + (size_t)r * MCOLS + m) = res;
        }
    }
}

extern "C" void kernel_launch(void* const* d_in, const int* in_sizes, int n_in,
                              void* d_out, int out_size)
{
    // Identify inputs by element count (all distinct):
    //   pred_logits 4194304 f32, pred_boxes 32768 f32,
    //   tgt_boxes 4096 f32, tgt_labels 2048 i32
    const float* logits = nullptr;
    const float* pboxes = nullptr;
    const float* tboxes = nullptr;
    const int*   tlabel = nullptr;
    for (int i = 0; i < n_in; i++) {
        switch (in_sizes[i]) {
            case 4194304: logits = (const float*)d_in[i]; break;
            case 32768:   pboxes = (const float*)d_in[i]; break;
            case 4096:    tboxes = (const float*)d_in[i]; break;
            case 2048:    tlabel = (const int*)  d_in[i]; break;
            default: break;
        }
    }

    const int smem = 64 * 1024;  // 16 KiB targets SoA + 8 KiB ids + 32 KiB probT
    cudaFuncSetAttribute(matcher_cost_kernel,
                         cudaFuncAttributeMaxDynamicSharedMemorySize, smem);

    dim3 grid(NROWS / ROWS_PB);  // 512 blocks
    dim3 block(256);
    matcher_cost_kernel<<<grid, block, smem>>>(logits, pboxes, tboxes, tlabel,
                                               (float*)d_out);
}